// round 5
// baseline (speedup 1.0000x reference)
#include <cuda_runtime.h>
#include <cstddef>

#define NE     80000
#define NN     8000
#define CC     128
#define HID    128
#define M0     7
#define FULLC  49
#define MALL   29
#define OUT2   896
#define LN_EPS 1e-5f
#define INV_RESCALE (1.0f / 23.395f)

typedef unsigned long long ull;

// d = a * b + d, two packed fp32 lanes (Blackwell f32x2)
#define FMA2(d, a, b) asm("fma.rn.f32x2 %0, %1, %2, %0;" : "+l"(d) : "l"(a), "l"(b))

__device__ __forceinline__ ull dup_f32(float x)
{
    unsigned u = __float_as_uint(x);
    return (ull)u | ((ull)u << 32);
}
__device__ __forceinline__ float lo_f32(ull v) { return __uint_as_float((unsigned)v); }
__device__ __forceinline__ float hi_f32(ull v) { return __uint_as_float((unsigned)(v >> 32)); }

// ---------------- scratch ----------------
__device__ float g_h[(size_t)NE * HID];     // post-activation hidden
__device__ float g_rad[(size_t)NE * OUT2];  // per-edge radial [E][7][128]
__device__ int   g_counts[NN];
__device__ int   g_offsets[NN + 1];
__device__ int   g_cursor[NN];
__device__ int   g_eids[NE];

// ---------------- CSR build ----------------
__global__ void k_zero()
{
    int i = blockIdx.x * blockDim.x + threadIdx.x;
    if (i < NN) { g_counts[i] = 0; g_cursor[i] = 0; }
}

__global__ void k_count(const int* __restrict__ ei)
{
    int e = blockIdx.x * blockDim.x + threadIdx.x;
    if (e < NE) atomicAdd(&g_counts[ei[NE + e]], 1);
}

__global__ void k_scan()
{
    __shared__ int s[1024];
    int carry = 0;
    for (int base = 0; base < NN; base += 1024) {
        int i = base + threadIdx.x;
        int v = (i < NN) ? g_counts[i] : 0;
        s[threadIdx.x] = v;
        __syncthreads();
        for (int off = 1; off < 1024; off <<= 1) {
            int t = (threadIdx.x >= off) ? s[threadIdx.x - off] : 0;
            __syncthreads();
            s[threadIdx.x] += t;
            __syncthreads();
        }
        if (i < NN) g_offsets[i] = carry + s[threadIdx.x] - v;
        int tot = s[1023];
        __syncthreads();
        carry += tot;
    }
    if (threadIdx.x == 0) g_offsets[NN] = carry;
}

__global__ void k_scatter(const int* __restrict__ ei)
{
    int e = blockIdx.x * blockDim.x + threadIdx.x;
    if (e < NE) {
        int d = ei[NE + e];
        int p = atomicAdd(&g_cursor[d], 1);
        g_eids[g_offsets[d] + p] = e;
    }
}

// ---------------- tiled fp32 GEMM with packed f32x2 FMA ----------------
// C = A[M,K] @ B[K,N] + bias.  64x64 tile, K-chunk 16, 256 threads, 4x4 microtile.
// A tile stored pre-duplicated ({a,a} per 64-bit lane); B pairs are natural.
__global__ __launch_bounds__(256) void k_gemm(
    const float* __restrict__ A, const float* __restrict__ B,
    const float* __restrict__ bias, float* __restrict__ C,
    int M, int N, int K)
{
    __shared__ ull   As2[16][64];   // duplicated A values
    __shared__ float Bs[16][64];
    const int tid = threadIdx.x;
    const int m0 = blockIdx.y * 64;
    const int n0 = blockIdx.x * 64;
    const int ty = tid >> 4, tx = tid & 15;
    const int lm = tid >> 2;
    const int lk = (tid & 3) * 4;
    const int bn = (tid & 15) * 4;
    const int bk = tid >> 4;

    ull acc2[4][2];
#pragma unroll
    for (int i = 0; i < 4; i++) { acc2[i][0] = 0ull; acc2[i][1] = 0ull; }

    for (int k0 = 0; k0 < K; k0 += 16) {
        float4 a4 = *reinterpret_cast<const float4*>(A + (size_t)(m0 + lm) * K + k0 + lk);
        As2[lk + 0][lm] = dup_f32(a4.x);
        As2[lk + 1][lm] = dup_f32(a4.y);
        As2[lk + 2][lm] = dup_f32(a4.z);
        As2[lk + 3][lm] = dup_f32(a4.w);
        *reinterpret_cast<float4*>(&Bs[bk][bn]) =
            *reinterpret_cast<const float4*>(B + (size_t)(k0 + bk) * N + n0 + bn);
        __syncthreads();
#pragma unroll
        for (int kk = 0; kk < 16; kk++) {
            ulonglong2 a01 = *reinterpret_cast<const ulonglong2*>(&As2[kk][ty * 4]);
            ulonglong2 a23 = *reinterpret_cast<const ulonglong2*>(&As2[kk][ty * 4 + 2]);
            ulonglong2 b   = *reinterpret_cast<const ulonglong2*>(&Bs[kk][tx * 4]);
            FMA2(acc2[0][0], a01.x, b.x);
            FMA2(acc2[0][1], a01.x, b.y);
            FMA2(acc2[1][0], a01.y, b.x);
            FMA2(acc2[1][1], a01.y, b.y);
            FMA2(acc2[2][0], a23.x, b.x);
            FMA2(acc2[2][1], a23.x, b.y);
            FMA2(acc2[3][0], a23.y, b.x);
            FMA2(acc2[3][1], a23.y, b.y);
        }
        __syncthreads();
    }

    float bb[4];
#pragma unroll
    for (int j = 0; j < 4; j++) bb[j] = bias[n0 + tx * 4 + j];
#pragma unroll
    for (int i = 0; i < 4; i++) {
        float4 o;
        o.x = lo_f32(acc2[i][0]) + bb[0];
        o.y = hi_f32(acc2[i][0]) + bb[1];
        o.z = lo_f32(acc2[i][1]) + bb[2];
        o.w = hi_f32(acc2[i][1]) + bb[3];
        *reinterpret_cast<float4*>(C + (size_t)(m0 + ty * 4 + i) * N + n0 + tx * 4) = o;
    }
}

// ---------------- LayerNorm + SiLU (in place), one warp per edge ----------------
__global__ void k_ln(const float* __restrict__ g1, const float* __restrict__ be1)
{
    int e = blockIdx.x * blockDim.y + threadIdx.y;
    if (e >= NE) return;
    int lane = threadIdx.x;
    float* hp = g_h + (size_t)e * HID;
    float4 v = reinterpret_cast<float4*>(hp)[lane];
    float s  = v.x + v.y + v.z + v.w;
    float ss = v.x * v.x + v.y * v.y + v.z * v.z + v.w * v.w;
#pragma unroll
    for (int o = 16; o > 0; o >>= 1) {
        s  += __shfl_xor_sync(0xffffffffu, s, o);
        ss += __shfl_xor_sync(0xffffffffu, ss, o);
    }
    float mu  = s * (1.0f / HID);
    float var = ss * (1.0f / HID) - mu * mu;
    float rs  = rsqrtf(var + LN_EPS);
    float4 g  = reinterpret_cast<const float4*>(g1)[lane];
    float4 be = reinterpret_cast<const float4*>(be1)[lane];
    float4 o;
    o.x = (v.x - mu) * rs * g.x + be.x;
    o.y = (v.y - mu) * rs * g.y + be.y;
    o.z = (v.z - mu) * rs * g.z + be.z;
    o.w = (v.w - mu) * rs * g.w + be.w;
    o.x = o.x / (1.0f + __expf(-o.x));
    o.y = o.y / (1.0f + __expf(-o.y));
    o.z = o.z / (1.0f + __expf(-o.z));
    o.w = o.w / (1.0f + __expf(-o.w));
    reinterpret_cast<float4*>(hp)[lane] = o;
}

// ---------------- per-node combine with f32x2 ----------------
// out[n] = x[n] + sum_e wig_e[49,7] @ rad_e[7,128] / R
// ws transposed to [m][f] (stride 52) so f-pairs are aligned 8B broadcasts.
#define WS_STRIDE 52
__global__ __launch_bounds__(128) void k_combine(
    const float* __restrict__ x, const float* __restrict__ wig,
    float* __restrict__ out)
{
    const int n = blockIdx.x;
    const int c = threadIdx.x;
    __shared__ float ws[M0 * WS_STRIDE];

    ull acc2[24];
#pragma unroll
    for (int fp = 0; fp < 24; fp++) acc2[fp] = 0ull;
    float acc48 = 0.f;

    const int beg = g_offsets[n];
    const int end = g_offsets[n + 1];
    for (int t = beg; t < end; t++) {
        const int e = g_eids[t];
        __syncthreads();  // protect ws reuse from previous edge
        const float* we = wig + (size_t)e * (FULLC * MALL);
        for (int i = c; i < FULLC * M0; i += 128) {
            int f = i / M0;
            int m = i - f * M0;
            ws[m * WS_STRIDE + f] = we[f * MALL + m] * INV_RESCALE;
        }
        __syncthreads();
        const float* re = g_rad + (size_t)e * OUT2 + c;
        float r[M0];
        ull  rd[M0];
#pragma unroll
        for (int m = 0; m < M0; m++) { r[m] = re[m * CC]; rd[m] = dup_f32(r[m]); }
#pragma unroll
        for (int m = 0; m < M0; m++) {
            const ull* wrow = reinterpret_cast<const ull*>(&ws[m * WS_STRIDE]);
#pragma unroll
            for (int fp = 0; fp < 24; fp++) FMA2(acc2[fp], rd[m], wrow[fp]);
            acc48 = fmaf(r[m], ws[m * WS_STRIDE + 48], acc48);
        }
    }

    const float* xb = x + (size_t)n * (FULLC * CC) + c;
    float* ob = out + (size_t)n * (FULLC * CC) + c;
#pragma unroll
    for (int fp = 0; fp < 24; fp++) {
        ob[(2 * fp)     * CC] = xb[(2 * fp)     * CC] + lo_f32(acc2[fp]);
        ob[(2 * fp + 1) * CC] = xb[(2 * fp + 1) * CC] + hi_f32(acc2[fp]);
    }
    ob[48 * CC] = xb[48 * CC] + acc48;
}

// ---------------- launch ----------------
extern "C" void kernel_launch(void* const* d_in, const int* in_sizes, int n_in,
                              void* d_out, int out_size)
{
    const float* x      = (const float*)d_in[0];
    const float* x_edge = (const float*)d_in[1];
    const float* wig    = (const float*)d_in[2];
    const float* W1     = (const float*)d_in[3];
    const float* b1     = (const float*)d_in[4];
    const float* g1     = (const float*)d_in[5];
    const float* be1    = (const float*)d_in[6];
    const float* W2     = (const float*)d_in[7];
    const float* b2     = (const float*)d_in[8];
    const int*   ei     = (const int*)d_in[9];   // int32 (JAX x64-disabled)
    float* out          = (float*)d_out;

    float* p_h   = nullptr;
    float* p_rad = nullptr;
    cudaGetSymbolAddress((void**)&p_h, g_h);
    cudaGetSymbolAddress((void**)&p_rad, g_rad);

    // Ordered so the big GEMM (W2) is the 4th launch — the slot ncu profiled last round.
    k_zero<<<(NN + 255) / 256, 256>>>();
    k_gemm<<<dim3(HID / 64, NE / 64), 256>>>(x_edge, W1, b1, p_h, NE, HID, HID);
    k_ln<<<NE / 8, dim3(32, 8)>>>(g1, be1);
    k_gemm<<<dim3(OUT2 / 64, NE / 64), 256>>>(p_h, W2, b2, p_rad, NE, OUT2, HID);
    k_count<<<(NE + 255) / 256, 256>>>(ei);
    k_scan<<<1, 1024>>>();
    k_scatter<<<(NE + 255) / 256, 256>>>(ei);
    k_combine<<<NN, 128>>>(x, wig, out);
}

// round 6
// speedup vs baseline: 1.8249x; 1.8249x over previous
#include <cuda_runtime.h>
#include <cuda_bf16.h>
#include <cstddef>

#define NE     80000
#define NN     8000
#define CC     128
#define HID    128
#define M0     7
#define FULLC  49
#define MALL   29
#define OUT2   896
#define LN_EPS 1e-5f
#define INV_RESCALE (1.0f / 23.395f)

// ---------------- scratch ----------------
__device__ float          g_h [(size_t)NE * HID];   // GEMM1 output (fp32)
__device__ __nv_bfloat16  g_hb[(size_t)NE * HID];   // LN+SiLU output (bf16, GEMM2 A operand)
__device__ __nv_bfloat16  g_w2b[(size_t)HID * OUT2];// W2 in bf16
__device__ float          g_rad[(size_t)NE * OUT2]; // per-edge radial [E][7][128]
__device__ int   g_counts[NN];
__device__ int   g_offsets[NN + 1];
__device__ int   g_cursor[NN];
__device__ int   g_eids[NE];

__device__ __forceinline__ unsigned sptr(const void* p)
{
    return (unsigned)__cvta_generic_to_shared(p);
}

// ---------------- CSR build ----------------
__global__ void k_zero()
{
    int i = blockIdx.x * blockDim.x + threadIdx.x;
    if (i < NN) { g_counts[i] = 0; g_cursor[i] = 0; }
}

__global__ void k_count(const int* __restrict__ ei)
{
    int e = blockIdx.x * blockDim.x + threadIdx.x;
    if (e < NE) atomicAdd(&g_counts[ei[NE + e]], 1);
}

__global__ void k_scan()
{
    __shared__ int s[1024];
    int carry = 0;
    for (int base = 0; base < NN; base += 1024) {
        int i = base + threadIdx.x;
        int v = (i < NN) ? g_counts[i] : 0;
        s[threadIdx.x] = v;
        __syncthreads();
        for (int off = 1; off < 1024; off <<= 1) {
            int t = (threadIdx.x >= off) ? s[threadIdx.x - off] : 0;
            __syncthreads();
            s[threadIdx.x] += t;
            __syncthreads();
        }
        if (i < NN) g_offsets[i] = carry + s[threadIdx.x] - v;
        int tot = s[1023];
        __syncthreads();
        carry += tot;
    }
    if (threadIdx.x == 0) g_offsets[NN] = carry;
}

__global__ void k_scatter(const int* __restrict__ ei)
{
    int e = blockIdx.x * blockDim.x + threadIdx.x;
    if (e < NE) {
        int d = ei[NE + e];
        int p = atomicAdd(&g_cursor[d], 1);
        g_eids[g_offsets[d] + p] = e;
    }
}

// ---------------- W2 -> bf16 ----------------
__global__ void k_cvtw2(const float* __restrict__ W2)
{
    int i = blockIdx.x * blockDim.x + threadIdx.x;
    if (i < HID * OUT2) g_w2b[i] = __float2bfloat16_rn(W2[i]);
}

// ---------------- GEMM1: plain fp32 tiled (R3-proven, ~95% fp32 peak) ----------------
__global__ __launch_bounds__(256) void k_gemm(
    const float* __restrict__ A, const float* __restrict__ B,
    const float* __restrict__ bias, float* __restrict__ C,
    int M, int N, int K)
{
    __shared__ float As[16][64];
    __shared__ float Bs[16][64];
    const int tid = threadIdx.x;
    const int m0 = blockIdx.y * 64;
    const int n0 = blockIdx.x * 64;
    const int ty = tid >> 4, tx = tid & 15;
    const int lm = tid >> 2;
    const int lk = (tid & 3) * 4;
    const int bn = (tid & 15) * 4;
    const int bk = tid >> 4;

    float acc[4][4];
#pragma unroll
    for (int i = 0; i < 4; i++)
#pragma unroll
        for (int j = 0; j < 4; j++) acc[i][j] = 0.f;

    for (int k0 = 0; k0 < K; k0 += 16) {
        float4 a4 = *reinterpret_cast<const float4*>(A + (size_t)(m0 + lm) * K + k0 + lk);
        As[lk + 0][lm] = a4.x;
        As[lk + 1][lm] = a4.y;
        As[lk + 2][lm] = a4.z;
        As[lk + 3][lm] = a4.w;
        *reinterpret_cast<float4*>(&Bs[bk][bn]) =
            *reinterpret_cast<const float4*>(B + (size_t)(k0 + bk) * N + n0 + bn);
        __syncthreads();
#pragma unroll
        for (int kk = 0; kk < 16; kk++) {
            float a[4], b[4];
            *reinterpret_cast<float4*>(a) = *reinterpret_cast<const float4*>(&As[kk][ty * 4]);
            *reinterpret_cast<float4*>(b) = *reinterpret_cast<const float4*>(&Bs[kk][tx * 4]);
#pragma unroll
            for (int i = 0; i < 4; i++)
#pragma unroll
                for (int j = 0; j < 4; j++) acc[i][j] += a[i] * b[j];
        }
        __syncthreads();
    }

    float bb[4];
#pragma unroll
    for (int j = 0; j < 4; j++) bb[j] = bias[n0 + tx * 4 + j];
#pragma unroll
    for (int i = 0; i < 4; i++) {
        float4 o;
        o.x = acc[i][0] + bb[0];
        o.y = acc[i][1] + bb[1];
        o.z = acc[i][2] + bb[2];
        o.w = acc[i][3] + bb[3];
        *reinterpret_cast<float4*>(C + (size_t)(m0 + ty * 4 + i) * N + n0 + tx * 4) = o;
    }
}

// ---------------- LayerNorm + SiLU: fp32 in -> bf16 out ----------------
__global__ void k_ln(const float* __restrict__ g1, const float* __restrict__ be1)
{
    int e = blockIdx.x * blockDim.y + threadIdx.y;
    if (e >= NE) return;
    int lane = threadIdx.x;
    const float* hp = g_h + (size_t)e * HID;
    float4 v = reinterpret_cast<const float4*>(hp)[lane];
    float s  = v.x + v.y + v.z + v.w;
    float ss = v.x * v.x + v.y * v.y + v.z * v.z + v.w * v.w;
#pragma unroll
    for (int o = 16; o > 0; o >>= 1) {
        s  += __shfl_xor_sync(0xffffffffu, s, o);
        ss += __shfl_xor_sync(0xffffffffu, ss, o);
    }
    float mu  = s * (1.0f / HID);
    float var = ss * (1.0f / HID) - mu * mu;
    float rs  = rsqrtf(var + LN_EPS);
    float4 g  = reinterpret_cast<const float4*>(g1)[lane];
    float4 be = reinterpret_cast<const float4*>(be1)[lane];
    float4 o;
    o.x = (v.x - mu) * rs * g.x + be.x;
    o.y = (v.y - mu) * rs * g.y + be.y;
    o.z = (v.z - mu) * rs * g.z + be.z;
    o.w = (v.w - mu) * rs * g.w + be.w;
    o.x = o.x / (1.0f + __expf(-o.x));
    o.y = o.y / (1.0f + __expf(-o.y));
    o.z = o.z / (1.0f + __expf(-o.z));
    o.w = o.w / (1.0f + __expf(-o.w));
    __nv_bfloat162 p0 = __floats2bfloat162_rn(o.x, o.y);
    __nv_bfloat162 p1 = __floats2bfloat162_rn(o.z, o.w);
    __nv_bfloat162* hb = reinterpret_cast<__nv_bfloat162*>(g_hb + (size_t)e * HID);
    hb[lane * 2]     = p0;
    hb[lane * 2 + 1] = p1;
}

// ---------------- GEMM2 on tensor cores: rad = hb @ W2b + b2 ----------------
// bf16 x bf16 -> fp32 via mma.sync m16n8k16. Block tile 128x128, full K=128 in smem.
// 8 warps: 4(M) x 2(N); warp tile 32M x 64N.
#define APAD_STRIDE 136  // 128 + 8 pad -> 272B rows, conflict-free ldmatrix
__global__ __launch_bounds__(256) void k_gemm2_mma(
    const float* __restrict__ b2, float* __restrict__ rad)
{
    extern __shared__ __align__(16) char smem_raw[];
    __nv_bfloat16* As = reinterpret_cast<__nv_bfloat16*>(smem_raw);
    __nv_bfloat16* Bs = As + 128 * APAD_STRIDE;

    const int tid  = threadIdx.x;
    const int lane = tid & 31;
    const int w    = tid >> 5;
    const int wm   = w & 3;       // warp M index (0..3)
    const int wn   = w >> 2;      // warp N index (0..1)
    const int m0   = blockIdx.y * 128;
    const int n0   = blockIdx.x * 128;

    // ---- load tiles: A = g_hb[m0..m0+127][0..127], B = g_w2b[0..127][n0..n0+127]
    {
        const int row  = tid >> 1;        // 0..127
        const int half = tid & 1;         // 0/1 -> 64 bf16 each
        const uint4* asrc = reinterpret_cast<const uint4*>(
            g_hb + (size_t)(m0 + row) * HID + half * 64);
        uint4* adst = reinterpret_cast<uint4*>(As + row * APAD_STRIDE + half * 64);
        const uint4* bsrc = reinterpret_cast<const uint4*>(
            g_w2b + (size_t)row * OUT2 + n0 + half * 64);
        uint4* bdst = reinterpret_cast<uint4*>(Bs + row * APAD_STRIDE + half * 64);
#pragma unroll
        for (int j = 0; j < 8; j++) adst[j] = asrc[j];
#pragma unroll
        for (int j = 0; j < 8; j++) bdst[j] = bsrc[j];
    }
    __syncthreads();

    float cf[2][8][4];
#pragma unroll
    for (int mt = 0; mt < 2; mt++)
#pragma unroll
        for (int nt = 0; nt < 8; nt++)
#pragma unroll
            for (int i = 0; i < 4; i++) cf[mt][nt][i] = 0.f;

    const int r    = lane & 7;
    const int quad = lane >> 3;

#pragma unroll
    for (int kc = 0; kc < 128; kc += 16) {
        // A fragments: two m16 tiles
        unsigned afr[2][4];
#pragma unroll
        for (int mt = 0; mt < 2; mt++) {
            int row = wm * 32 + mt * 16 + r + ((quad & 1) ? 8 : 0);
            int col = kc + ((quad & 2) ? 8 : 0);
            unsigned addr = sptr(&As[row * APAD_STRIDE + col]);
            asm volatile("ldmatrix.sync.aligned.m8n8.x4.shared.b16 {%0,%1,%2,%3}, [%4];"
                         : "=r"(afr[mt][0]), "=r"(afr[mt][1]),
                           "=r"(afr[mt][2]), "=r"(afr[mt][3])
                         : "r"(addr));
        }
        // B fragments: four n16 tiles (trans)
        unsigned bfr[4][4];
#pragma unroll
        for (int nt16 = 0; nt16 < 4; nt16++) {
            int krow = kc + r + ((quad & 1) ? 8 : 0);
            int ncol = wn * 64 + nt16 * 16 + ((quad & 2) ? 8 : 0);
            unsigned addr = sptr(&Bs[krow * APAD_STRIDE + ncol]);
            asm volatile("ldmatrix.sync.aligned.m8n8.x4.trans.shared.b16 {%0,%1,%2,%3}, [%4];"
                         : "=r"(bfr[nt16][0]), "=r"(bfr[nt16][1]),
                           "=r"(bfr[nt16][2]), "=r"(bfr[nt16][3])
                         : "r"(addr));
        }
#pragma unroll
        for (int mt = 0; mt < 2; mt++)
#pragma unroll
            for (int nt = 0; nt < 8; nt++) {
                unsigned b0 = bfr[nt >> 1][(nt & 1) ? 2 : 0];
                unsigned b1 = bfr[nt >> 1][(nt & 1) ? 3 : 1];
                asm volatile(
                    "mma.sync.aligned.m16n8k16.row.col.f32.bf16.bf16.f32 "
                    "{%0,%1,%2,%3}, {%4,%5,%6,%7}, {%8,%9}, {%0,%1,%2,%3};"
                    : "+f"(cf[mt][nt][0]), "+f"(cf[mt][nt][1]),
                      "+f"(cf[mt][nt][2]), "+f"(cf[mt][nt][3])
                    : "r"(afr[mt][0]), "r"(afr[mt][1]),
                      "r"(afr[mt][2]), "r"(afr[mt][3]),
                      "r"(b0), "r"(b1));
            }
    }

    // ---- epilogue: += bias, store fp32
#pragma unroll
    for (int mt = 0; mt < 2; mt++) {
        int row = m0 + wm * 32 + mt * 16 + (lane >> 2);
#pragma unroll
        for (int nt = 0; nt < 8; nt++) {
            int col = n0 + wn * 64 + nt * 8 + (lane & 3) * 2;
            float ba = b2[col], bb = b2[col + 1];
            float2 lo = make_float2(cf[mt][nt][0] + ba, cf[mt][nt][1] + bb);
            float2 hi = make_float2(cf[mt][nt][2] + ba, cf[mt][nt][3] + bb);
            *reinterpret_cast<float2*>(rad + (size_t)row * OUT2 + col)       = lo;
            *reinterpret_cast<float2*>(rad + (size_t)(row + 8) * OUT2 + col) = hi;
        }
    }
}

// ---------------- per-node combine (R3-proven scalar) ----------------
__global__ __launch_bounds__(128) void k_combine(
    const float* __restrict__ x, const float* __restrict__ wig,
    float* __restrict__ out)
{
    const int n = blockIdx.x;
    const int c = threadIdx.x;
    __shared__ float ws[FULLC * M0];

    float acc[FULLC];
#pragma unroll
    for (int f = 0; f < FULLC; f++) acc[f] = 0.f;

    const int beg = g_offsets[n];
    const int end = g_offsets[n + 1];
    for (int t = beg; t < end; t++) {
        const int e = g_eids[t];
        __syncthreads();
        const float* we = wig + (size_t)e * (FULLC * MALL);
        for (int i = c; i < FULLC * M0; i += 128) {
            int f = i / M0;
            int m = i - f * M0;
            ws[i] = we[f * MALL + m] * INV_RESCALE;
        }
        __syncthreads();
        const float* re = g_rad + (size_t)e * OUT2 + c;
        float r[M0];
#pragma unroll
        for (int m = 0; m < M0; m++) r[m] = re[m * CC];
#pragma unroll
        for (int f = 0; f < FULLC; f++) {
            float sfm = acc[f];
#pragma unroll
            for (int m = 0; m < M0; m++) sfm += ws[f * M0 + m] * r[m];
            acc[f] = sfm;
        }
    }

    const float* xb = x + (size_t)n * (FULLC * CC) + c;
    float* ob = out + (size_t)n * (FULLC * CC) + c;
#pragma unroll
    for (int f = 0; f < FULLC; f++) ob[f * CC] = xb[f * CC] + acc[f];
}

// ---------------- launch ----------------
extern "C" void kernel_launch(void* const* d_in, const int* in_sizes, int n_in,
                              void* d_out, int out_size)
{
    const float* x      = (const float*)d_in[0];
    const float* x_edge = (const float*)d_in[1];
    const float* wig    = (const float*)d_in[2];
    const float* W1     = (const float*)d_in[3];
    const float* b1     = (const float*)d_in[4];
    const float* g1     = (const float*)d_in[5];
    const float* be1    = (const float*)d_in[6];
    const float* W2     = (const float*)d_in[7];
    const float* b2     = (const float*)d_in[8];
    const int*   ei     = (const int*)d_in[9];   // int32 (JAX x64-disabled)
    float* out          = (float*)d_out;

    float* p_h   = nullptr;
    float* p_rad = nullptr;
    cudaGetSymbolAddress((void**)&p_h, g_h);
    cudaGetSymbolAddress((void**)&p_rad, g_rad);

    const int smem2 = 2 * 128 * APAD_STRIDE * (int)sizeof(__nv_bfloat16);  // 69632 B
    cudaFuncSetAttribute(k_gemm2_mma, cudaFuncAttributeMaxDynamicSharedMemorySize, smem2);

    // order keeps the MMA GEMM at launch index 3 (the slot ncu captures)
    k_gemm<<<dim3(HID / 64, NE / 64), 256>>>(x_edge, W1, b1, p_h, NE, HID, HID);
    k_cvtw2<<<(HID * OUT2 + 255) / 256, 256>>>(W2);
    k_ln<<<NE / 8, dim3(32, 8)>>>(g1, be1);
    k_gemm2_mma<<<dim3(OUT2 / 128, NE / 128), 256, smem2>>>(b2, p_rad);
    k_zero<<<(NN + 255) / 256, 256>>>();
    k_count<<<(NE + 255) / 256, 256>>>(ei);
    k_scan<<<1, 1024>>>();
    k_scatter<<<(NE + 255) / 256, 256>>>(ei);
    k_combine<<<NN, 128>>>(x, wig, out);
}